// round 16
// baseline (speedup 1.0000x reference)
#include <cuda_runtime.h>
#include <cuda_bf16.h>
#include <cuda_fp16.h>
#include <math.h>
#include <stdint.h>

#define NB   8
#define NT   12
#define BTT  96
#define NN   10000
#define NH   64
#define NC   2
#define NE   320000
#define ROWS (BTT*NN)    // 960000

// ======================= mma.sync helpers ===================================
__device__ __forceinline__ uint32_t smem_to_u32(const void* p) {
    uint32_t a;
    asm("{ .reg .u64 t; cvta.to.shared.u64 t, %1; cvt.u32.u64 %0, t; }" : "=r"(a) : "l"(p));
    return a;
}
__device__ __forceinline__ void ldsm4(uint32_t* r, uint32_t addr) {
    asm volatile("ldmatrix.sync.aligned.m8n8.x4.shared.b16 {%0,%1,%2,%3}, [%4];"
        : "=r"(r[0]), "=r"(r[1]), "=r"(r[2]), "=r"(r[3]) : "r"(addr));
}
__device__ __forceinline__ void ldsm2(uint32_t* r, uint32_t addr) {
    asm volatile("ldmatrix.sync.aligned.m8n8.x2.shared.b16 {%0,%1}, [%2];"
        : "=r"(r[0]), "=r"(r[1]) : "r"(addr));
}
// fp16 x fp16 -> fp32 MMA
__device__ __forceinline__ void mma16816h(float* c, const uint32_t* a, const uint32_t* b) {
    asm volatile(
        "mma.sync.aligned.m16n8k16.row.col.f32.f16.f16.f32 "
        "{%0,%1,%2,%3}, {%4,%5,%6,%7}, {%8,%9}, {%0,%1,%2,%3};"
        : "+f"(c[0]), "+f"(c[1]), "+f"(c[2]), "+f"(c[3])
        : "r"(a[0]), "r"(a[1]), "r"(a[2]), "r"(a[3]), "r"(b[0]), "r"(b[1]));
}
// split fp32 pair into fp16 hi + fp16 residual words
__device__ __forceinline__ void split_pair_f16(float x0, float x1, uint32_t& hi, uint32_t& lo) {
    __half h0 = __float2half_rn(x0), h1 = __float2half_rn(x1);
    __half l0 = __float2half_rn(x0 - __half2float(h0));
    __half l1 = __float2half_rn(x1 - __half2float(h1));
    __half2 H = __halves2half2(h0, h1), L = __halves2half2(l0, l1);
    hi = *(uint32_t*)&H; lo = *(uint32_t*)&L;
}

// ======================= scratch (fp16 intermediates only) ==================
__device__ __half g_T0h [ROWS*NH];
__device__ __half g_Tx1h[ROWS*NH];
__device__ __half g_Tx2h[ROWS*NH];
__device__ __half g_chebh[ROWS*NH];

__device__ float g_deg[NN];
__device__ float g_dis[NN];
__device__ int   g_cnt[NN];
__device__ int   g_off[NN+1];
__device__ int   g_cur[NN];
__device__ int   g_csr_col[NE];
__device__ float g_csr_w[NE];
__device__ float g_Wcat[192*64];
__device__ float g_Wtc2[3*192*64];

// ======================= graph preprocessing ================================
__global__ void zero_kernel() {
    int i = blockIdx.x*256 + threadIdx.x;
    if (i < NN) { g_deg[i] = 0.f; g_cnt[i] = 0; g_cur[i] = 0; }
}
__global__ void degcnt_kernel(const int* __restrict__ ei, const float* __restrict__ ew) {
    int e = blockIdx.x*256 + threadIdx.x;
    if (e < NE) {
        int r = ei[e];
        atomicAdd(&g_deg[r], ew[e]);
        atomicAdd(&g_cnt[r], 1);
    }
}
__global__ void dis_kernel() {
    int i = blockIdx.x*256 + threadIdx.x;
    if (i < NN) {
        float d = g_deg[i];
        g_dis[i] = d > 0.f ? rsqrtf(d) : 0.f;
    }
}
__global__ void scan_kernel() {
    __shared__ int sums[1024];
    int tid = threadIdx.x;
    const int CH = (NN + 1023) / 1024;
    int base = tid * CH;
    int s = 0;
    for (int i = 0; i < CH; i++) { int idx = base + i; if (idx < NN) s += g_cnt[idx]; }
    sums[tid] = s;
    __syncthreads();
    for (int d = 1; d < 1024; d <<= 1) {
        int v = (tid >= d) ? sums[tid - d] : 0;
        __syncthreads();
        sums[tid] += v;
        __syncthreads();
    }
    int run = sums[tid] - s;
    for (int i = 0; i < CH; i++) {
        int idx = base + i;
        if (idx < NN) { g_off[idx] = run; run += g_cnt[idx]; }
    }
    if (tid == 1023) g_off[NN] = sums[1023];
}
__global__ void scatter_kernel(const int* __restrict__ ei, const float* __restrict__ ew) {
    int e = blockIdx.x*256 + threadIdx.x;
    if (e < NE) {
        int r = ei[e];
        int c = ei[NE + e];
        int pos = g_off[r] + atomicAdd(&g_cur[r], 1);
        g_csr_col[pos] = c;
        g_csr_w[pos]   = -g_dis[r] * ew[e] * g_dis[c];
    }
}

// ======================= weight repacking ===================================
__global__ void wcat_kernel(const float* __restrict__ W) {
    int idx = blockIdx.x*256 + threadIdx.x;
    if (idx >= 192*64) return;
    int k = idx >> 6, j = idx & 63;
    float v;
    if (k < 64)       v = W[k*64 + j] - W[2*4096 + k*64 + j];
    else if (k < 128) v = W[4096 + (k-64)*64 + j];
    else              v = 2.f * W[2*4096 + (k-128)*64 + j];
    g_Wcat[idx] = v;
}
__global__ void wtc2_kernel(const float* __restrict__ w1,
                            const float* __restrict__ w2,
                            const float* __restrict__ w3) {
    int idx = blockIdx.x*256 + threadIdx.x;
    if (idx >= 3*192*64) return;
    int j = idx / 12288;
    int r = idx - j*12288;
    int k = r >> 6, h = r & 63;
    int dt = k >> 6;
    int c  = k & 63;
    const float* w = (j == 0) ? w1 : (j == 1) ? w2 : w3;
    g_Wtc2[idx] = w[h*192 + c*3 + dt];
}

// ======================= TC1: 32 rows/block, 8 h per thread =================
__global__ __launch_bounds__(256) void tc1_kernel(const float* __restrict__ X,
                           const float* __restrict__ w1, const float* __restrict__ b1,
                           const float* __restrict__ w2, const float* __restrict__ b2,
                           const float* __restrict__ w3, const float* __restrict__ b3) {
    __shared__ float s1[384], s2[384], s3[384];
    __shared__ float sb[3][64];
    __shared__ float sxv[32][6];
    int tid = threadIdx.x;
    for (int i = tid; i < 384; i += 256) { s1[i] = w1[i]; s2[i] = w2[i]; s3[i] = w3[i]; }
    if (tid < 64) { sb[0][tid] = b1[tid]; sb[1][tid] = b2[tid]; sb[2][tid] = b3[tid]; }
    int row0 = blockIdx.x * 32;
    if (tid < 192) {
        int r = tid / 6, q = tid % 6;
        int k = q >> 1, c = q & 1;
        int row = row0 + r;
        int bt = row / NN, n = row - bt*NN;
        int b = bt / NT, t = bt - b*NT;
        int tt = t + k - 1;
        float v = 0.f;
        if (tt >= 0 && tt < NT) v = X[(((b*NT + tt)*NN) + n)*NC + c];
        sxv[r][q] = v;
    }
    __syncthreads();
    int r = tid >> 3;
    int h0 = (tid & 7) * 8;
    float x[6];
    #pragma unroll
    for (int q = 0; q < 6; q++) x[q] = sxv[r][q];
    __half out8[8];
    #pragma unroll
    for (int i = 0; i < 8; i++) {
        int h = h0 + i;
        float p = sb[0][h], q = sb[1][h], rr = sb[2][h];
        #pragma unroll
        for (int k = 0; k < 3; k++)
            #pragma unroll
            for (int c = 0; c < 2; c++) {
                float xv = x[k*2 + c];
                int wi = h*6 + c*3 + k;
                p += s1[wi]*xv; q += s2[wi]*xv; rr += s3[wi]*xv;
            }
        float sg = 1.f / (1.f + expf(-q));
        out8[i] = __float2half(fmaxf(p*sg + rr, 0.f));
    }
    *(uint4*)&g_T0h[((size_t)(row0 + r))*NH + h0] = *(uint4*)out8;
}

// ======================= prop: smem-staged edges, 32 bt per block ===========
__device__ __forceinline__ void facc(float4& a, float w, uint2 u) {
    float2 p01 = __half22float2(*(__half2*)&u.x);
    float2 p23 = __half22float2(*(__half2*)&u.y);
    a.x += w*p01.x; a.y += w*p01.y; a.z += w*p23.x; a.w += w*p23.y;
}

__global__ __launch_bounds__(256) void prop_smem(const __half* __restrict__ srcH,
                                                 __half* __restrict__ dstH) {
    __shared__ int   s_col[256];
    __shared__ float s_w[256];
    int n   = blockIdx.x;
    int bt0 = blockIdx.y * 32;
    int tid = threadIdx.x;
    int btl = tid >> 4, hq = tid & 15;
    int e0 = g_off[n], e1 = g_off[n+1];
    const uint2* xs = (const uint2*)srcH;
    float4 accA = make_float4(0.f,0.f,0.f,0.f);
    float4 accB = make_float4(0.f,0.f,0.f,0.f);
    int baseA = (bt0 + btl) * NN;
    int baseB = (bt0 + 16 + btl) * NN;

    for (int ce = e0; ce < e1; ce += 256) {
        int m = e1 - ce; if (m > 256) m = 256;
        __syncthreads();
        if (tid < m) {
            s_col[tid] = g_csr_col[ce + tid];
            s_w[tid]   = g_csr_w[ce + tid];
        }
        __syncthreads();
        int i = 0;
        for (; i + 3 < m; i += 4) {
            int   c0 = s_col[i],   c1 = s_col[i+1], c2 = s_col[i+2], c3 = s_col[i+3];
            float w0 = s_w[i],     w1 = s_w[i+1],   w2 = s_w[i+2],   w3 = s_w[i+3];
            uint2 uA0 = __ldg(&xs[(baseA + c0)*16 + hq]);
            uint2 uB0 = __ldg(&xs[(baseB + c0)*16 + hq]);
            uint2 uA1 = __ldg(&xs[(baseA + c1)*16 + hq]);
            uint2 uB1 = __ldg(&xs[(baseB + c1)*16 + hq]);
            uint2 uA2 = __ldg(&xs[(baseA + c2)*16 + hq]);
            uint2 uB2 = __ldg(&xs[(baseB + c2)*16 + hq]);
            uint2 uA3 = __ldg(&xs[(baseA + c3)*16 + hq]);
            uint2 uB3 = __ldg(&xs[(baseB + c3)*16 + hq]);
            facc(accA, w0, uA0); facc(accB, w0, uB0);
            facc(accA, w1, uA1); facc(accB, w1, uB1);
            facc(accA, w2, uA2); facc(accB, w2, uB2);
            facc(accA, w3, uA3); facc(accB, w3, uB3);
        }
        for (; i < m; i++) {
            int   c = s_col[i];
            float w = s_w[i];
            uint2 uA = __ldg(&xs[(baseA + c)*16 + hq]);
            uint2 uB = __ldg(&xs[(baseB + c)*16 + hq]);
            facc(accA, w, uA); facc(accB, w, uB);
        }
    }
    __half2 a01 = __floats2half2_rn(accA.x, accA.y);
    __half2 a23 = __floats2half2_rn(accA.z, accA.w);
    __half2 b01 = __floats2half2_rn(accB.x, accB.y);
    __half2 b23 = __floats2half2_rn(accB.z, accB.w);
    uint2 ha, hb;
    ha.x = *(uint32_t*)&a01; ha.y = *(uint32_t*)&a23;
    hb.x = *(uint32_t*)&b01; hb.y = *(uint32_t*)&b23;
    ((uint2*)dstH)[(baseA + n)*16 + hq] = ha;
    ((uint2*)dstH)[(baseB + n)*16 + hq] = hb;
}

// ======================= cheb GEMM: fp16 MMA, A exact, B hi/lo ==============
#define GC_AH   1024
#define GC_BH   19456
#define GC_BL   47104
#define GC_SMEM 74752

__global__ __launch_bounds__(256) void gemm_cheb_mma(const float* __restrict__ cheb_b) {
    extern __shared__ char smem[];
    uint32_t sb = smem_to_u32(smem);
    int tid = threadIdx.x, warp = tid >> 5, lane = tid & 31;
    int warpM = warp >> 2, warpN = warp & 3;

    if (tid < 64) ((float*)smem)[tid] = cheb_b[tid];
    for (int p = tid; p < 6144; p += 256) {
        int n = p / 96;
        int kp = (p - n*96) * 2;
        int chunk = kp >> 6, kin = kp & 63;
        float w0 = g_Wcat[kp*64 + n];
        float w1 = g_Wcat[(kp+1)*64 + n];
        uint32_t hi, lo;
        split_pair_f16(w0, w1, hi, lo);
        int off = (chunk*64 + n)*144 + kin*2;
        *(uint32_t*)(smem + GC_BH + off) = hi;
        *(uint32_t*)(smem + GC_BL + off) = lo;
    }
    __syncthreads();

    const float* bias = (const float*)smem;
    int ar = tid >> 1;
    int ac0 = (tid & 1) * 32;
    int g = lane >> 2, tg = lane & 3;

    for (int tile = blockIdx.x; tile < ROWS/128; tile += gridDim.x) {
        int row0 = tile*128;
        float acc[4][2][4];
        #pragma unroll
        for (int mt = 0; mt < 4; mt++)
            #pragma unroll
            for (int nt = 0; nt < 2; nt++)
                #pragma unroll
                for (int i = 0; i < 4; i++) acc[mt][nt][i] = 0.f;

        uint4 pref[4];
        {
            const uint4* pp = (const uint4*)(g_T0h + ((size_t)(row0 + ar))*64 + ac0);
            #pragma unroll
            for (int i = 0; i < 4; i++) pref[i] = pp[i];
        }
        #pragma unroll
        for (int chunk = 0; chunk < 3; chunk++) {
            uint32_t* dh = (uint32_t*)(smem + GC_AH + ar*144 + ac0*2);
            #pragma unroll
            for (int i = 0; i < 4; i++) {
                dh[i*4+0] = pref[i].x;
                dh[i*4+1] = pref[i].y;
                dh[i*4+2] = pref[i].z;
                dh[i*4+3] = pref[i].w;
            }
            if (chunk < 2) {
                const __half* src = (chunk == 0) ? g_Tx1h : g_Tx2h;
                const uint4* pp = (const uint4*)(src + ((size_t)(row0 + ar))*64 + ac0);
                #pragma unroll
                for (int i = 0; i < 4; i++) pref[i] = pp[i];
            }
            __syncthreads();
            #pragma unroll
            for (int ks = 0; ks < 4; ks++) {
                int k0 = ks * 16;
                uint32_t ah[4][4];
                int arow = warpM*64 + ((lane>>3)&1)*8 + (lane&7);
                int acolb = (k0 + ((lane>>4)&1)*8) * 2;
                #pragma unroll
                for (int mt = 0; mt < 4; mt++) {
                    uint32_t ad = sb + GC_AH + (arow + mt*16)*144 + acolb;
                    ldsm4(ah[mt], ad);
                }
                int l4 = lane & 15;
                int brow = warpN*16 + (l4 & 7);
                int bcolb = (k0 + ((l4>>3)&1)*8) * 2;
                #pragma unroll
                for (int nt = 0; nt < 2; nt++) {
                    uint32_t bh[2], bl[2];
                    uint32_t bd = sb + GC_BH + (chunk*64 + brow + nt*8)*144 + bcolb;
                    ldsm2(bh, bd);
                    ldsm2(bl, bd + (GC_BL - GC_BH));
                    #pragma unroll
                    for (int mt = 0; mt < 4; mt++) {
                        mma16816h(acc[mt][nt], ah[mt], bh);
                        mma16816h(acc[mt][nt], ah[mt], bl);
                    }
                }
            }
            __syncthreads();
        }
        #pragma unroll
        for (int mt = 0; mt < 4; mt++) {
            int row = row0 + warpM*64 + mt*16 + g;
            #pragma unroll
            for (int nt = 0; nt < 2; nt++) {
                int c = warpN*16 + nt*8 + tg*2;
                float v00 = fmaxf(acc[mt][nt][0] + bias[c],   0.f);
                float v01 = fmaxf(acc[mt][nt][1] + bias[c+1], 0.f);
                float v10 = fmaxf(acc[mt][nt][2] + bias[c],   0.f);
                float v11 = fmaxf(acc[mt][nt][3] + bias[c+1], 0.f);
                __half2 h0 = __floats2half2_rn(v00, v01);
                __half2 h1 = __floats2half2_rn(v10, v11);
                *(uint32_t*)&g_chebh[(size_t)row*64 + c]     = *(uint32_t*)&h0;
                *(uint32_t*)&g_chebh[(size_t)(row+8)*64 + c] = *(uint32_t*)&h1;
            }
        }
    }
}

// ======================= TC2: fp16 MMA, gate-interleaved N ==================
#define T2_AH   1024
#define T2_BH   19456
#define T2_BL   102400
#define T2_SMEM 185344
#define NTILE_N 79
#define T2_TILES (BTT*NTILE_N)

__global__ __launch_bounds__(256) void tc2_mma(const float* __restrict__ b1,
                                               const float* __restrict__ b2,
                                               const float* __restrict__ b3,
                                               float* __restrict__ out) {
    extern __shared__ char smem[];
    uint32_t sb = smem_to_u32(smem);
    int tid = threadIdx.x, warp = tid >> 5, lane = tid & 31;
    int warpM = warp >> 2, warpN = warp & 3;

    if (tid < 64) {
        ((float*)smem)[tid]       = b1[tid];
        ((float*)smem)[64 + tid]  = b2[tid];
        ((float*)smem)[128 + tid] = b3[tid];
    }
    for (int p = tid; p < 18432; p += 256) {
        int n = p / 96;
        int kp = (p - n*96) * 2;
        int chunk = kp >> 6, kin = kp & 63;
        int gate = n >> 6, h = n & 63;
        float w0 = g_Wtc2[gate*12288 + kp*64 + h];
        float w1 = g_Wtc2[gate*12288 + (kp+1)*64 + h];
        uint32_t hi, lo;
        split_pair_f16(w0, w1, hi, lo);
        int off = (chunk*192 + n)*144 + kin*2;
        *(uint32_t*)(smem + T2_BH + off) = hi;
        *(uint32_t*)(smem + T2_BL + off) = lo;
    }
    __syncthreads();

    const float* bP = (const float*)smem;
    const float* bQ = bP + 64;
    const float* bR = bP + 128;
    int ar = tid >> 1;
    int ac0 = (tid & 1) * 32;
    int g = lane >> 2, tg = lane & 3;

    for (int tt = blockIdx.x; tt < T2_TILES; tt += gridDim.x) {
        int bt = tt / NTILE_N, ntile = tt - bt*NTILE_N;
        int b = bt / NT, t = bt - b*NT;
        int an = ntile*128 + ar;

        float acc[4][6][4];
        #pragma unroll
        for (int mt = 0; mt < 4; mt++)
            #pragma unroll
            for (int nt = 0; nt < 6; nt++)
                #pragma unroll
                for (int i = 0; i < 4; i++) acc[mt][nt][i] = 0.f;

        const uint4* pdt[3];
        #pragma unroll
        for (int dt = 0; dt < 3; dt++) {
            int ttm = t + dt - 1;
            pdt[dt] = ((an < NN) && ttm >= 0 && ttm < NT)
                    ? (const uint4*)(g_chebh + ((size_t)((b*NT + ttm)*NN + an))*64 + ac0)
                    : (const uint4*)0;
        }
        uint4 zero4; zero4.x = zero4.y = zero4.z = zero4.w = 0;
        uint4 pref[4];
        #pragma unroll
        for (int i = 0; i < 4; i++)
            pref[i] = pdt[0] ? pdt[0][i] : zero4;

        #pragma unroll
        for (int chunk = 0; chunk < 3; chunk++) {
            uint32_t* dh = (uint32_t*)(smem + T2_AH + ar*144 + ac0*2);
            #pragma unroll
            for (int i = 0; i < 4; i++) {
                dh[i*4+0] = pref[i].x;
                dh[i*4+1] = pref[i].y;
                dh[i*4+2] = pref[i].z;
                dh[i*4+3] = pref[i].w;
            }
            if (chunk < 2) {
                const uint4* pp = pdt[chunk+1];
                #pragma unroll
                for (int i = 0; i < 4; i++)
                    pref[i] = pp ? pp[i] : zero4;
            }
            __syncthreads();
            #pragma unroll
            for (int ks = 0; ks < 4; ks++) {
                int k0 = ks * 16;
                uint32_t ah[4][4];
                int arow = warpM*64 + ((lane>>3)&1)*8 + (lane&7);
                int acolb = (k0 + ((lane>>4)&1)*8) * 2;
                #pragma unroll
                for (int mt = 0; mt < 4; mt++) {
                    uint32_t ad = sb + T2_AH + (arow + mt*16)*144 + acolb;
                    ldsm4(ah[mt], ad);
                }
                int l4 = lane & 15;
                int bcolb = (k0 + ((l4>>3)&1)*8) * 2;
                #pragma unroll
                for (int nt = 0; nt < 6; nt++) {
                    int gate = nt >> 1, j = nt & 1;
                    int brow = gate*64 + warpN*16 + j*8 + (l4 & 7);
                    uint32_t bh[2], bl[2];
                    uint32_t bd = sb + T2_BH + (chunk*192 + brow)*144 + bcolb;
                    ldsm2(bh, bd);
                    ldsm2(bl, bd + (T2_BL - T2_BH));
                    #pragma unroll
                    for (int mt = 0; mt < 4; mt++) {
                        mma16816h(acc[mt][nt], ah[mt], bh);
                        mma16816h(acc[mt][nt], ah[mt], bl);
                    }
                }
            }
            __syncthreads();
        }
        #pragma unroll
        for (int mt = 0; mt < 4; mt++) {
            int n = ntile*128 + warpM*64 + mt*16 + g;
            #pragma unroll
            for (int j = 0; j < 2; j++) {
                int h = warpN*16 + j*8 + tg*2;
                float pb0 = bP[h], pb1 = bP[h+1];
                float qb0 = bQ[h], qb1 = bQ[h+1];
                float rb0 = bR[h], rb1 = bR[h+1];
                if (n < NN) {
                    float P0 = acc[mt][j][0] + pb0,   P1 = acc[mt][j][1] + pb1;
                    float Q0 = acc[mt][2+j][0] + qb0, Q1 = acc[mt][2+j][1] + qb1;
                    float R0 = acc[mt][4+j][0] + rb0, R1 = acc[mt][4+j][1] + rb1;
                    float s0 = 1.f / (1.f + expf(-Q0));
                    float s1 = 1.f / (1.f + expf(-Q1));
                    float2 o = make_float2(fmaxf(P0*s0 + R0, 0.f), fmaxf(P1*s1 + R1, 0.f));
                    *(float2*)&out[((size_t)bt*NN + n)*64 + h] = o;
                }
                if (n + 8 < NN) {
                    float P0 = acc[mt][j][2] + pb0,   P1 = acc[mt][j][3] + pb1;
                    float Q0 = acc[mt][2+j][2] + qb0, Q1 = acc[mt][2+j][3] + qb1;
                    float R0 = acc[mt][4+j][2] + rb0, R1 = acc[mt][4+j][3] + rb1;
                    float s0 = 1.f / (1.f + expf(-Q0));
                    float s1 = 1.f / (1.f + expf(-Q1));
                    float2 o = make_float2(fmaxf(P0*s0 + R0, 0.f), fmaxf(P1*s1 + R1, 0.f));
                    *(float2*)&out[((size_t)bt*NN + n + 8)*64 + h] = o;
                }
            }
        }
    }
}

// ======================= launcher ===========================================
extern "C" void kernel_launch(void* const* d_in, const int* in_sizes, int n_in,
                              void* d_out, int out_size) {
    const float* X     = (const float*)d_in[0];
    const int*   ei    = (const int*)  d_in[1];
    const float* ew    = (const float*)d_in[2];
    const float* t1w1  = (const float*)d_in[3];
    const float* t1b1  = (const float*)d_in[4];
    const float* t1w2  = (const float*)d_in[5];
    const float* t1b2  = (const float*)d_in[6];
    const float* t1w3  = (const float*)d_in[7];
    const float* t1b3  = (const float*)d_in[8];
    const float* chebW = (const float*)d_in[9];
    const float* chebB = (const float*)d_in[10];
    const float* t2w1  = (const float*)d_in[11];
    const float* t2b1  = (const float*)d_in[12];
    const float* t2w2  = (const float*)d_in[13];
    const float* t2b2  = (const float*)d_in[14];
    const float* t2w3  = (const float*)d_in[15];
    const float* t2b3  = (const float*)d_in[16];
    float* out = (float*)d_out;

    static int configured = 0;
    if (!configured) {
        cudaFuncSetAttribute(gemm_cheb_mma, cudaFuncAttributeMaxDynamicSharedMemorySize, GC_SMEM);
        cudaFuncSetAttribute(tc2_mma,       cudaFuncAttributeMaxDynamicSharedMemorySize, T2_SMEM);
        configured = 1;
    }

    __half* T0h  = 0; cudaGetSymbolAddress((void**)&T0h,  g_T0h);
    __half* Tx1h = 0; cudaGetSymbolAddress((void**)&Tx1h, g_Tx1h);
    __half* Tx2h = 0; cudaGetSymbolAddress((void**)&Tx2h, g_Tx2h);

    zero_kernel   <<<(NN + 255)/256, 256>>>();
    degcnt_kernel <<<(NE + 255)/256, 256>>>(ei, ew);
    dis_kernel    <<<(NN + 255)/256, 256>>>();
    scan_kernel   <<<1, 1024>>>();
    scatter_kernel<<<(NE + 255)/256, 256>>>(ei, ew);

    wcat_kernel<<<(192*64 + 255)/256, 256>>>(chebW);
    wtc2_kernel<<<(3*192*64 + 255)/256, 256>>>(t2w1, t2w2, t2w3);

    tc1_kernel<<<ROWS/32, 256>>>(X, t1w1, t1b1, t1w2, t1b2, t1w3, t1b3);

    prop_smem<<<dim3(NN, 3), 256>>>(T0h,  Tx1h);
    prop_smem<<<dim3(NN, 3), 256>>>(Tx1h, Tx2h);

    gemm_cheb_mma<<<296, 256, GC_SMEM>>>(chebB);

    tc2_mma<<<148, 256, T2_SMEM>>>(t2b1, t2b2, t2b3, out);
}

// round 17
// speedup vs baseline: 1.7588x; 1.7588x over previous
#include <cuda_runtime.h>
#include <cuda_bf16.h>
#include <cuda_fp16.h>
#include <math.h>
#include <stdint.h>

#define NB   8
#define NT   12
#define BTT  96
#define NN   10000
#define NH   64
#define NC   2
#define NE   320000
#define ROWS (BTT*NN)    // 960000

// ======================= mma.sync helpers ===================================
__device__ __forceinline__ uint32_t smem_to_u32(const void* p) {
    uint32_t a;
    asm("{ .reg .u64 t; cvta.to.shared.u64 t, %1; cvt.u32.u64 %0, t; }" : "=r"(a) : "l"(p));
    return a;
}
__device__ __forceinline__ void ldsm4(uint32_t* r, uint32_t addr) {
    asm volatile("ldmatrix.sync.aligned.m8n8.x4.shared.b16 {%0,%1,%2,%3}, [%4];"
        : "=r"(r[0]), "=r"(r[1]), "=r"(r[2]), "=r"(r[3]) : "r"(addr));
}
__device__ __forceinline__ void ldsm2(uint32_t* r, uint32_t addr) {
    asm volatile("ldmatrix.sync.aligned.m8n8.x2.shared.b16 {%0,%1}, [%2];"
        : "=r"(r[0]), "=r"(r[1]) : "r"(addr));
}
// fp16 x fp16 -> fp32 MMA
__device__ __forceinline__ void mma16816h(float* c, const uint32_t* a, const uint32_t* b) {
    asm volatile(
        "mma.sync.aligned.m16n8k16.row.col.f32.f16.f16.f32 "
        "{%0,%1,%2,%3}, {%4,%5,%6,%7}, {%8,%9}, {%0,%1,%2,%3};"
        : "+f"(c[0]), "+f"(c[1]), "+f"(c[2]), "+f"(c[3])
        : "r"(a[0]), "r"(a[1]), "r"(a[2]), "r"(a[3]), "r"(b[0]), "r"(b[1]));
}
// split fp32 pair into fp16 hi + fp16 residual words
__device__ __forceinline__ void split_pair_f16(float x0, float x1, uint32_t& hi, uint32_t& lo) {
    __half h0 = __float2half_rn(x0), h1 = __float2half_rn(x1);
    __half l0 = __float2half_rn(x0 - __half2float(h0));
    __half l1 = __float2half_rn(x1 - __half2float(h1));
    __half2 H = __halves2half2(h0, h1), L = __halves2half2(l0, l1);
    hi = *(uint32_t*)&H; lo = *(uint32_t*)&L;
}

// ======================= scratch (fp16 intermediates only) ==================
__device__ __half g_T0h [ROWS*NH];
__device__ __half g_Tx1h[ROWS*NH];
__device__ __half g_Tx2h[ROWS*NH];
__device__ __half g_chebh[ROWS*NH];

__device__ float g_deg[NN];
__device__ float g_dis[NN];
__device__ int   g_cnt[NN];
__device__ int   g_off[NN+1];
__device__ int   g_cur[NN];
__device__ int   g_csr_col[NE];
__device__ float g_csr_w[NE];
__device__ float g_Wcat[192*64];
__device__ float g_Wtc2[3*192*64];

// ======================= graph preprocessing ================================
__global__ void zero_kernel() {
    int i = blockIdx.x*256 + threadIdx.x;
    if (i < NN) { g_deg[i] = 0.f; g_cnt[i] = 0; g_cur[i] = 0; }
}
__global__ void degcnt_kernel(const int* __restrict__ ei, const float* __restrict__ ew) {
    int e = blockIdx.x*256 + threadIdx.x;
    if (e < NE) {
        int r = ei[e];
        atomicAdd(&g_deg[r], ew[e]);
        atomicAdd(&g_cnt[r], 1);
    }
}
__global__ void dis_kernel() {
    int i = blockIdx.x*256 + threadIdx.x;
    if (i < NN) {
        float d = g_deg[i];
        g_dis[i] = d > 0.f ? rsqrtf(d) : 0.f;
    }
}
__global__ void scan_kernel() {
    __shared__ int sums[1024];
    int tid = threadIdx.x;
    const int CH = (NN + 1023) / 1024;
    int base = tid * CH;
    int s = 0;
    for (int i = 0; i < CH; i++) { int idx = base + i; if (idx < NN) s += g_cnt[idx]; }
    sums[tid] = s;
    __syncthreads();
    for (int d = 1; d < 1024; d <<= 1) {
        int v = (tid >= d) ? sums[tid - d] : 0;
        __syncthreads();
        sums[tid] += v;
        __syncthreads();
    }
    int run = sums[tid] - s;
    for (int i = 0; i < CH; i++) {
        int idx = base + i;
        if (idx < NN) { g_off[idx] = run; run += g_cnt[idx]; }
    }
    if (tid == 1023) g_off[NN] = sums[1023];
}
__global__ void scatter_kernel(const int* __restrict__ ei, const float* __restrict__ ew) {
    int e = blockIdx.x*256 + threadIdx.x;
    if (e < NE) {
        int r = ei[e];
        int c = ei[NE + e];
        int pos = g_off[r] + atomicAdd(&g_cur[r], 1);
        g_csr_col[pos] = c;
        g_csr_w[pos]   = -g_dis[r] * ew[e] * g_dis[c];
    }
}

// ======================= weight repacking ===================================
__global__ void wcat_kernel(const float* __restrict__ W) {
    int idx = blockIdx.x*256 + threadIdx.x;
    if (idx >= 192*64) return;
    int k = idx >> 6, j = idx & 63;
    float v;
    if (k < 64)       v = W[k*64 + j] - W[2*4096 + k*64 + j];
    else if (k < 128) v = W[4096 + (k-64)*64 + j];
    else              v = 2.f * W[2*4096 + (k-128)*64 + j];
    g_Wcat[idx] = v;
}
__global__ void wtc2_kernel(const float* __restrict__ w1,
                            const float* __restrict__ w2,
                            const float* __restrict__ w3) {
    int idx = blockIdx.x*256 + threadIdx.x;
    if (idx >= 3*192*64) return;
    int j = idx / 12288;
    int r = idx - j*12288;
    int k = r >> 6, h = r & 63;
    int dt = k >> 6;
    int c  = k & 63;
    const float* w = (j == 0) ? w1 : (j == 1) ? w2 : w3;
    g_Wtc2[idx] = w[h*192 + c*3 + dt];
}

// ======================= TC1 (R15 version, fp16 out) ========================
__global__ void tc1_kernel(const float* __restrict__ X,
                           const float* __restrict__ w1, const float* __restrict__ b1,
                           const float* __restrict__ w2, const float* __restrict__ b2,
                           const float* __restrict__ w3, const float* __restrict__ b3) {
    __shared__ float s1[384], s2[384], s3[384];
    __shared__ float sb[3][64];
    __shared__ float sx[4][8];
    int tid = threadIdx.x;
    for (int i = tid; i < 384; i += 256) { s1[i] = w1[i]; s2[i] = w2[i]; s3[i] = w3[i]; }
    if (tid < 64) { sb[0][tid] = b1[tid]; sb[1][tid] = b2[tid]; sb[2][tid] = b3[tid]; }
    int bt = blockIdx.y;
    int b = bt / NT, t = bt - b*NT;
    int n0 = blockIdx.x * 4;
    if (tid < 24) {
        int nl = tid / 6, idx = tid % 6;
        int k = idx >> 1, c = idx & 1;
        int tt = t + k - 1;
        float v = 0.f;
        if (tt >= 0 && tt < NT) v = X[(((b*NT + tt)*NN) + (n0 + nl))*NC + c];
        sx[nl][k*2 + c] = v;
    }
    __syncthreads();
    int h = tid & 63, nl = tid >> 6;
    float p = sb[0][h], q = sb[1][h], r = sb[2][h];
    #pragma unroll
    for (int k = 0; k < 3; k++)
        #pragma unroll
        for (int c = 0; c < 2; c++) {
            float xv = sx[nl][k*2 + c];
            int wi = h*6 + c*3 + k;
            p += s1[wi]*xv; q += s2[wi]*xv; r += s3[wi]*xv;
        }
    float sg = 1.f / (1.f + expf(-q));
    float o  = fmaxf(p*sg + r, 0.f);
    g_T0h[((size_t)bt*NN + n0 + nl)*NH + h] = __float2half(o);
}

// ======================= prop: smem-staged edges, 32 bt per block ===========
__device__ __forceinline__ void facc(float4& a, float w, uint2 u) {
    float2 p01 = __half22float2(*(__half2*)&u.x);
    float2 p23 = __half22float2(*(__half2*)&u.y);
    a.x += w*p01.x; a.y += w*p01.y; a.z += w*p23.x; a.w += w*p23.y;
}

__global__ __launch_bounds__(256) void prop_smem(const __half* __restrict__ srcH,
                                                 __half* __restrict__ dstH) {
    __shared__ int   s_col[256];
    __shared__ float s_w[256];
    int n   = blockIdx.x;
    int bt0 = blockIdx.y * 32;
    int tid = threadIdx.x;
    int btl = tid >> 4, hq = tid & 15;
    int e0 = g_off[n], e1 = g_off[n+1];
    const uint2* xs = (const uint2*)srcH;
    float4 accA = make_float4(0.f,0.f,0.f,0.f);
    float4 accB = make_float4(0.f,0.f,0.f,0.f);
    int baseA = (bt0 + btl) * NN;
    int baseB = (bt0 + 16 + btl) * NN;

    for (int ce = e0; ce < e1; ce += 256) {
        int m = e1 - ce; if (m > 256) m = 256;
        __syncthreads();
        if (tid < m) {
            s_col[tid] = g_csr_col[ce + tid];
            s_w[tid]   = g_csr_w[ce + tid];
        }
        __syncthreads();
        int i = 0;
        for (; i + 3 < m; i += 4) {
            int   c0 = s_col[i],   c1 = s_col[i+1], c2 = s_col[i+2], c3 = s_col[i+3];
            float w0 = s_w[i],     w1 = s_w[i+1],   w2 = s_w[i+2],   w3 = s_w[i+3];
            uint2 uA0 = __ldg(&xs[(baseA + c0)*16 + hq]);
            uint2 uB0 = __ldg(&xs[(baseB + c0)*16 + hq]);
            uint2 uA1 = __ldg(&xs[(baseA + c1)*16 + hq]);
            uint2 uB1 = __ldg(&xs[(baseB + c1)*16 + hq]);
            uint2 uA2 = __ldg(&xs[(baseA + c2)*16 + hq]);
            uint2 uB2 = __ldg(&xs[(baseB + c2)*16 + hq]);
            uint2 uA3 = __ldg(&xs[(baseA + c3)*16 + hq]);
            uint2 uB3 = __ldg(&xs[(baseB + c3)*16 + hq]);
            facc(accA, w0, uA0); facc(accB, w0, uB0);
            facc(accA, w1, uA1); facc(accB, w1, uB1);
            facc(accA, w2, uA2); facc(accB, w2, uB2);
            facc(accA, w3, uA3); facc(accB, w3, uB3);
        }
        for (; i < m; i++) {
            int   c = s_col[i];
            float w = s_w[i];
            uint2 uA = __ldg(&xs[(baseA + c)*16 + hq]);
            uint2 uB = __ldg(&xs[(baseB + c)*16 + hq]);
            facc(accA, w, uA); facc(accB, w, uB);
        }
    }
    __half2 a01 = __floats2half2_rn(accA.x, accA.y);
    __half2 a23 = __floats2half2_rn(accA.z, accA.w);
    __half2 b01 = __floats2half2_rn(accB.x, accB.y);
    __half2 b23 = __floats2half2_rn(accB.z, accB.w);
    uint2 ha, hb;
    ha.x = *(uint32_t*)&a01; ha.y = *(uint32_t*)&a23;
    hb.x = *(uint32_t*)&b01; hb.y = *(uint32_t*)&b23;
    ((uint2*)dstH)[(baseA + n)*16 + hq] = ha;
    ((uint2*)dstH)[(baseB + n)*16 + hq] = hb;
}

// ======================= cheb GEMM: fp16 MMA, A exact, B hi/lo ==============
#define GC_AH   1024
#define GC_BH   19456
#define GC_BL   47104
#define GC_SMEM 74752

__global__ __launch_bounds__(256) void gemm_cheb_mma(const float* __restrict__ cheb_b) {
    extern __shared__ char smem[];
    uint32_t sb = smem_to_u32(smem);
    int tid = threadIdx.x, warp = tid >> 5, lane = tid & 31;
    int warpM = warp >> 2, warpN = warp & 3;

    if (tid < 64) ((float*)smem)[tid] = cheb_b[tid];
    for (int p = tid; p < 6144; p += 256) {
        int n = p / 96;
        int kp = (p - n*96) * 2;
        int chunk = kp >> 6, kin = kp & 63;
        float w0 = g_Wcat[kp*64 + n];
        float w1 = g_Wcat[(kp+1)*64 + n];
        uint32_t hi, lo;
        split_pair_f16(w0, w1, hi, lo);
        int off = (chunk*64 + n)*144 + kin*2;
        *(uint32_t*)(smem + GC_BH + off) = hi;
        *(uint32_t*)(smem + GC_BL + off) = lo;
    }
    __syncthreads();

    const float* bias = (const float*)smem;
    int ar = tid >> 1;
    int ac0 = (tid & 1) * 32;
    int g = lane >> 2, tg = lane & 3;

    for (int tile = blockIdx.x; tile < ROWS/128; tile += gridDim.x) {
        int row0 = tile*128;
        float acc[4][2][4];
        #pragma unroll
        for (int mt = 0; mt < 4; mt++)
            #pragma unroll
            for (int nt = 0; nt < 2; nt++)
                #pragma unroll
                for (int i = 0; i < 4; i++) acc[mt][nt][i] = 0.f;

        uint4 pref[4];
        {
            const uint4* pp = (const uint4*)(g_T0h + ((size_t)(row0 + ar))*64 + ac0);
            #pragma unroll
            for (int i = 0; i < 4; i++) pref[i] = pp[i];
        }
        #pragma unroll
        for (int chunk = 0; chunk < 3; chunk++) {
            uint32_t* dh = (uint32_t*)(smem + GC_AH + ar*144 + ac0*2);
            #pragma unroll
            for (int i = 0; i < 4; i++) {
                dh[i*4+0] = pref[i].x;
                dh[i*4+1] = pref[i].y;
                dh[i*4+2] = pref[i].z;
                dh[i*4+3] = pref[i].w;
            }
            if (chunk < 2) {
                const __half* src = (chunk == 0) ? g_Tx1h : g_Tx2h;
                const uint4* pp = (const uint4*)(src + ((size_t)(row0 + ar))*64 + ac0);
                #pragma unroll
                for (int i = 0; i < 4; i++) pref[i] = pp[i];
            }
            __syncthreads();
            #pragma unroll
            for (int ks = 0; ks < 4; ks++) {
                int k0 = ks * 16;
                uint32_t ah[4][4];
                int arow = warpM*64 + ((lane>>3)&1)*8 + (lane&7);
                int acolb = (k0 + ((lane>>4)&1)*8) * 2;
                #pragma unroll
                for (int mt = 0; mt < 4; mt++) {
                    uint32_t ad = sb + GC_AH + (arow + mt*16)*144 + acolb;
                    ldsm4(ah[mt], ad);
                }
                int l4 = lane & 15;
                int brow = warpN*16 + (l4 & 7);
                int bcolb = (k0 + ((l4>>3)&1)*8) * 2;
                #pragma unroll
                for (int nt = 0; nt < 2; nt++) {
                    uint32_t bh[2], bl[2];
                    uint32_t bd = sb + GC_BH + (chunk*64 + brow + nt*8)*144 + bcolb;
                    ldsm2(bh, bd);
                    ldsm2(bl, bd + (GC_BL - GC_BH));
                    #pragma unroll
                    for (int mt = 0; mt < 4; mt++) {
                        mma16816h(acc[mt][nt], ah[mt], bh);
                        mma16816h(acc[mt][nt], ah[mt], bl);
                    }
                }
            }
            __syncthreads();
        }
        #pragma unroll
        for (int mt = 0; mt < 4; mt++) {
            int row = row0 + warpM*64 + mt*16 + g;
            #pragma unroll
            for (int nt = 0; nt < 2; nt++) {
                int c = warpN*16 + nt*8 + tg*2;
                float v00 = fmaxf(acc[mt][nt][0] + bias[c],   0.f);
                float v01 = fmaxf(acc[mt][nt][1] + bias[c+1], 0.f);
                float v10 = fmaxf(acc[mt][nt][2] + bias[c],   0.f);
                float v11 = fmaxf(acc[mt][nt][3] + bias[c+1], 0.f);
                __half2 h0 = __floats2half2_rn(v00, v01);
                __half2 h1 = __floats2half2_rn(v10, v11);
                *(uint32_t*)&g_chebh[(size_t)row*64 + c]     = *(uint32_t*)&h0;
                *(uint32_t*)&g_chebh[(size_t)(row+8)*64 + c] = *(uint32_t*)&h1;
            }
        }
    }
}

// ======================= TC2: fp16 MMA, gate-interleaved N ==================
#define T2_AH   1024
#define T2_BH   19456
#define T2_BL   102400
#define T2_SMEM 185344
#define NTILE_N 79
#define T2_TILES (BTT*NTILE_N)

__global__ __launch_bounds__(256) void tc2_mma(const float* __restrict__ b1,
                                               const float* __restrict__ b2,
                                               const float* __restrict__ b3,
                                               float* __restrict__ out) {
    extern __shared__ char smem[];
    uint32_t sb = smem_to_u32(smem);
    int tid = threadIdx.x, warp = tid >> 5, lane = tid & 31;
    int warpM = warp >> 2, warpN = warp & 3;

    if (tid < 64) {
        ((float*)smem)[tid]       = b1[tid];
        ((float*)smem)[64 + tid]  = b2[tid];
        ((float*)smem)[128 + tid] = b3[tid];
    }
    for (int p = tid; p < 18432; p += 256) {
        int n = p / 96;
        int kp = (p - n*96) * 2;
        int chunk = kp >> 6, kin = kp & 63;
        int gate = n >> 6, h = n & 63;
        float w0 = g_Wtc2[gate*12288 + kp*64 + h];
        float w1 = g_Wtc2[gate*12288 + (kp+1)*64 + h];
        uint32_t hi, lo;
        split_pair_f16(w0, w1, hi, lo);
        int off = (chunk*192 + n)*144 + kin*2;
        *(uint32_t*)(smem + T2_BH + off) = hi;
        *(uint32_t*)(smem + T2_BL + off) = lo;
    }
    __syncthreads();

    const float* bP = (const float*)smem;
    const float* bQ = bP + 64;
    const float* bR = bP + 128;
    int ar = tid >> 1;
    int ac0 = (tid & 1) * 32;
    int g = lane >> 2, tg = lane & 3;

    for (int tt = blockIdx.x; tt < T2_TILES; tt += gridDim.x) {
        int bt = tt / NTILE_N, ntile = tt - bt*NTILE_N;
        int b = bt / NT, t = bt - b*NT;
        int an = ntile*128 + ar;

        float acc[4][6][4];
        #pragma unroll
        for (int mt = 0; mt < 4; mt++)
            #pragma unroll
            for (int nt = 0; nt < 6; nt++)
                #pragma unroll
                for (int i = 0; i < 4; i++) acc[mt][nt][i] = 0.f;

        const uint4* pdt[3];
        #pragma unroll
        for (int dt = 0; dt < 3; dt++) {
            int ttm = t + dt - 1;
            pdt[dt] = ((an < NN) && ttm >= 0 && ttm < NT)
                    ? (const uint4*)(g_chebh + ((size_t)((b*NT + ttm)*NN + an))*64 + ac0)
                    : (const uint4*)0;
        }
        uint4 zero4; zero4.x = zero4.y = zero4.z = zero4.w = 0;
        uint4 pref[4];
        #pragma unroll
        for (int i = 0; i < 4; i++)
            pref[i] = pdt[0] ? pdt[0][i] : zero4;

        #pragma unroll
        for (int chunk = 0; chunk < 3; chunk++) {
            uint32_t* dh = (uint32_t*)(smem + T2_AH + ar*144 + ac0*2);
            #pragma unroll
            for (int i = 0; i < 4; i++) {
                dh[i*4+0] = pref[i].x;
                dh[i*4+1] = pref[i].y;
                dh[i*4+2] = pref[i].z;
                dh[i*4+3] = pref[i].w;
            }
            if (chunk < 2) {
                const uint4* pp = pdt[chunk+1];
                #pragma unroll
                for (int i = 0; i < 4; i++)
                    pref[i] = pp ? pp[i] : zero4;
            }
            __syncthreads();
            #pragma unroll
            for (int ks = 0; ks < 4; ks++) {
                int k0 = ks * 16;
                uint32_t ah[4][4];
                int arow = warpM*64 + ((lane>>3)&1)*8 + (lane&7);
                int acolb = (k0 + ((lane>>4)&1)*8) * 2;
                #pragma unroll
                for (int mt = 0; mt < 4; mt++) {
                    uint32_t ad = sb + T2_AH + (arow + mt*16)*144 + acolb;
                    ldsm4(ah[mt], ad);
                }
                int l4 = lane & 15;
                int bcolb = (k0 + ((l4>>3)&1)*8) * 2;
                #pragma unroll
                for (int nt = 0; nt < 6; nt++) {
                    int gate = nt >> 1, j = nt & 1;
                    int brow = gate*64 + warpN*16 + j*8 + (l4 & 7);
                    uint32_t bh[2], bl[2];
                    uint32_t bd = sb + T2_BH + (chunk*192 + brow)*144 + bcolb;
                    ldsm2(bh, bd);
                    ldsm2(bl, bd + (T2_BL - T2_BH));
                    #pragma unroll
                    for (int mt = 0; mt < 4; mt++) {
                        mma16816h(acc[mt][nt], ah[mt], bh);
                        mma16816h(acc[mt][nt], ah[mt], bl);
                    }
                }
            }
            __syncthreads();
        }
        #pragma unroll
        for (int mt = 0; mt < 4; mt++) {
            int n = ntile*128 + warpM*64 + mt*16 + g;
            #pragma unroll
            for (int j = 0; j < 2; j++) {
                int h = warpN*16 + j*8 + tg*2;
                float pb0 = bP[h], pb1 = bP[h+1];
                float qb0 = bQ[h], qb1 = bQ[h+1];
                float rb0 = bR[h], rb1 = bR[h+1];
                if (n < NN) {
                    float P0 = acc[mt][j][0] + pb0,   P1 = acc[mt][j][1] + pb1;
                    float Q0 = acc[mt][2+j][0] + qb0, Q1 = acc[mt][2+j][1] + qb1;
                    float R0 = acc[mt][4+j][0] + rb0, R1 = acc[mt][4+j][1] + rb1;
                    float s0 = 1.f / (1.f + expf(-Q0));
                    float s1 = 1.f / (1.f + expf(-Q1));
                    float2 o = make_float2(fmaxf(P0*s0 + R0, 0.f), fmaxf(P1*s1 + R1, 0.f));
                    *(float2*)&out[((size_t)bt*NN + n)*64 + h] = o;
                }
                if (n + 8 < NN) {
                    float P0 = acc[mt][j][2] + pb0,   P1 = acc[mt][j][3] + pb1;
                    float Q0 = acc[mt][2+j][2] + qb0, Q1 = acc[mt][2+j][3] + qb1;
                    float R0 = acc[mt][4+j][2] + rb0, R1 = acc[mt][4+j][3] + rb1;
                    float s0 = 1.f / (1.f + expf(-Q0));
                    float s1 = 1.f / (1.f + expf(-Q1));
                    float2 o = make_float2(fmaxf(P0*s0 + R0, 0.f), fmaxf(P1*s1 + R1, 0.f));
                    *(float2*)&out[((size_t)bt*NN + n + 8)*64 + h] = o;
                }
            }
        }
    }
}

// ======================= launcher ===========================================
extern "C" void kernel_launch(void* const* d_in, const int* in_sizes, int n_in,
                              void* d_out, int out_size) {
    const float* X     = (const float*)d_in[0];
    const int*   ei    = (const int*)  d_in[1];
    const float* ew    = (const float*)d_in[2];
    const float* t1w1  = (const float*)d_in[3];
    const float* t1b1  = (const float*)d_in[4];
    const float* t1w2  = (const float*)d_in[5];
    const float* t1b2  = (const float*)d_in[6];
    const float* t1w3  = (const float*)d_in[7];
    const float* t1b3  = (const float*)d_in[8];
    const float* chebW = (const float*)d_in[9];
    const float* chebB = (const float*)d_in[10];
    const float* t2w1  = (const float*)d_in[11];
    const float* t2b1  = (const float*)d_in[12];
    const float* t2w2  = (const float*)d_in[13];
    const float* t2b2  = (const float*)d_in[14];
    const float* t2w3  = (const float*)d_in[15];
    const float* t2b3  = (const float*)d_in[16];
    float* out = (float*)d_out;

    static int configured = 0;
    if (!configured) {
        cudaFuncSetAttribute(gemm_cheb_mma, cudaFuncAttributeMaxDynamicSharedMemorySize, GC_SMEM);
        cudaFuncSetAttribute(tc2_mma,       cudaFuncAttributeMaxDynamicSharedMemorySize, T2_SMEM);
        configured = 1;
    }

    __half* T0h  = 0; cudaGetSymbolAddress((void**)&T0h,  g_T0h);
    __half* Tx1h = 0; cudaGetSymbolAddress((void**)&Tx1h, g_Tx1h);
    __half* Tx2h = 0; cudaGetSymbolAddress((void**)&Tx2h, g_Tx2h);

    zero_kernel   <<<(NN + 255)/256, 256>>>();
    degcnt_kernel <<<(NE + 255)/256, 256>>>(ei, ew);
    dis_kernel    <<<(NN + 255)/256, 256>>>();
    scan_kernel   <<<1, 1024>>>();
    scatter_kernel<<<(NE + 255)/256, 256>>>(ei, ew);

    wcat_kernel<<<(192*64 + 255)/256, 256>>>(chebW);
    wtc2_kernel<<<(3*192*64 + 255)/256, 256>>>(t2w1, t2w2, t2w3);

    tc1_kernel<<<dim3(NN/4, BTT), 256>>>(X, t1w1, t1b1, t1w2, t1b2, t1w3, t1b3);

    prop_smem<<<dim3(NN, 3), 256>>>(T0h,  Tx1h);
    prop_smem<<<dim3(NN, 3), 256>>>(Tx1h, Tx2h);

    gemm_cheb_mma<<<296, 256, GC_SMEM>>>(chebB);

    tc2_mma<<<148, 256, T2_SMEM>>>(t2b1, t2b2, t2b3, out);
}